// round 4
// baseline (speedup 1.0000x reference)
#include <cuda_runtime.h>
#include <cstdint>

#define VV 4096
#define HH 128
#define MVV 20
#define NMAX 50000
#define ETYPES_MAX 512
#define BMAX 64

// ---------------- static scratch (no runtime allocation allowed) ----------------
__device__ __align__(16) float g_xA[(size_t)NMAX * HH];
__device__ __align__(16) float g_xB[(size_t)NMAX * HH];
__device__ __align__(16) float g_node_lin[VV * HH];
__device__ __align__(16) float g_edge_lin[ETYPES_MAX * HH];
__device__ __align__(16) float g_relmsg[ETYPES_MAX * HH];
__device__ __align__(16) float g_attn[BMAX * VV];
__device__ float g_beta[BMAX * MVV];
__device__ __align__(16) float g_pooled[BMAX * HH];
__device__ float g_cnt[BMAX];
__device__ __align__(16) float g_logits[(size_t)BMAX * MVV * VV];  // 21 MB

// ================= tf32 tensor-core GEMM: C[r,c] = sum_k A[r,k]*B[c,k] =================
// A: [M][4096] row-major (visit_node flattened), B: [4096][4096] row-major (alpha_w layer)
// block tile 128x128, k-step 32, 8 warps (2x4), warp tile 64x32, mma m16n8k8.
// smem layout [k][m] (+4 pad) -> fragment LDS are conflict-free (addr%32 = 4*tig+gid).
__global__ __launch_bounds__(256) void tf32_gemm_kernel(
    const float* __restrict__ A, const float* __restrict__ Bm, float* __restrict__ C)
{
    __shared__ float sA[32][132];
    __shared__ float sB[32][132];

    const int tid = threadIdx.x;
    const int warpId = tid >> 5, lane = tid & 31;
    const int wr = warpId >> 2, wc = warpId & 3;
    const int gid = lane >> 2, tig = lane & 3;
    const int rbase = blockIdx.y * 128;
    const int cbase = blockIdx.x * 128;

    const int mrow = tid >> 3;        // 0..31 (then +32*i)
    const int kq = (tid & 7) * 4;     // k offset within 32

    float4 ra[4], rb[4];
    float acc[4][4][4];
#pragma unroll
    for (int i = 0; i < 4; i++)
#pragma unroll
        for (int j = 0; j < 4; j++)
#pragma unroll
            for (int q = 0; q < 4; q++) acc[i][j][q] = 0.f;

#pragma unroll
    for (int i = 0; i < 4; i++) {
        ra[i] = *reinterpret_cast<const float4*>(A + (size_t)(rbase + mrow + 32 * i) * VV + kq);
        rb[i] = *reinterpret_cast<const float4*>(Bm + (size_t)(cbase + mrow + 32 * i) * VV + kq);
    }

    for (int kt = 0; kt < VV / 32; kt++) {
        // store staged regs to smem (tf32-convert once here)
#pragma unroll
        for (int i = 0; i < 4; i++) {
            int m = mrow + 32 * i;
            float v[4] = {ra[i].x, ra[i].y, ra[i].z, ra[i].w};
            float w[4] = {rb[i].x, rb[i].y, rb[i].z, rb[i].w};
#pragma unroll
            for (int j = 0; j < 4; j++) {
                uint32_t ta, tb;
                asm("cvt.rna.tf32.f32 %0, %1;" : "=r"(ta) : "f"(v[j]));
                asm("cvt.rna.tf32.f32 %0, %1;" : "=r"(tb) : "f"(w[j]));
                sA[kq + j][m] = __uint_as_float(ta);
                sB[kq + j][m] = __uint_as_float(tb);
            }
        }
        __syncthreads();

        if (kt + 1 < VV / 32) {
            const float* Ap = A + (size_t)(kt + 1) * 32 + kq;
            const float* Bp = Bm + (size_t)(kt + 1) * 32 + kq;
#pragma unroll
            for (int i = 0; i < 4; i++) {
                ra[i] = *reinterpret_cast<const float4*>(Ap + (size_t)(rbase + mrow + 32 * i) * VV);
                rb[i] = *reinterpret_cast<const float4*>(Bp + (size_t)(cbase + mrow + 32 * i) * VV);
            }
        }

#pragma unroll
        for (int ks = 0; ks < 4; ks++) {
            const int k0 = ks * 8;
            uint32_t af[4][4], bf[4][2];
#pragma unroll
            for (int mf = 0; mf < 4; mf++) {
                int r0 = wr * 64 + mf * 16 + gid;
                af[mf][0] = __float_as_uint(sA[k0 + tig][r0]);
                af[mf][1] = __float_as_uint(sA[k0 + tig][r0 + 8]);
                af[mf][2] = __float_as_uint(sA[k0 + tig + 4][r0]);
                af[mf][3] = __float_as_uint(sA[k0 + tig + 4][r0 + 8]);
            }
#pragma unroll
            for (int nf = 0; nf < 4; nf++) {
                int c0 = wc * 32 + nf * 8 + gid;
                bf[nf][0] = __float_as_uint(sB[k0 + tig][c0]);
                bf[nf][1] = __float_as_uint(sB[k0 + tig + 4][c0]);
            }
#pragma unroll
            for (int mf = 0; mf < 4; mf++)
#pragma unroll
                for (int nf = 0; nf < 4; nf++) {
                    asm volatile(
                        "mma.sync.aligned.m16n8k8.row.col.f32.tf32.tf32.f32 "
                        "{%0,%1,%2,%3}, {%4,%5,%6,%7}, {%8,%9}, {%0,%1,%2,%3};"
                        : "+f"(acc[mf][nf][0]), "+f"(acc[mf][nf][1]),
                          "+f"(acc[mf][nf][2]), "+f"(acc[mf][nf][3])
                        : "r"(af[mf][0]), "r"(af[mf][1]), "r"(af[mf][2]), "r"(af[mf][3]),
                          "r"(bf[nf][0]), "r"(bf[nf][1]));
                }
        }
        __syncthreads();
    }

#pragma unroll
    for (int mf = 0; mf < 4; mf++) {
        int r0 = rbase + wr * 64 + mf * 16 + gid;
#pragma unroll
        for (int nf = 0; nf < 4; nf++) {
            int c0 = cbase + wc * 32 + nf * 8 + tig * 2;
            *reinterpret_cast<float2*>(C + (size_t)r0 * VV + c0) =
                make_float2(acc[mf][nf][0], acc[mf][nf][1]);
            *reinterpret_cast<float2*>(C + (size_t)(r0 + 8) * VV + c0) =
                make_float2(acc[mf][nf][2], acc[mf][nf][3]);
        }
    }
}

// ---------------- softmax over MV + beta reduce: attn[b,v] ----------------
__global__ __launch_bounds__(256) void softmax_beta_kernel(
    const float* __restrict__ logits, const float* __restrict__ beta,
    float* __restrict__ attn)
{
    __shared__ float sBeta[MVV];
    const int b = blockIdx.y;
    const int v = blockIdx.x * 256 + threadIdx.x;
    if (threadIdx.x < MVV) sBeta[threadIdx.x] = beta[b * MVV + threadIdx.x];
    __syncthreads();
    const float* lp = logits + (size_t)b * MVV * VV + v;
    float z[MVV];
    float mx = -1e30f;
#pragma unroll
    for (int m = 0; m < MVV; m++) {
        z[m] = lp[(size_t)m * VV];
        mx = fmaxf(mx, z[m]);
    }
    float se = 0.f, sw = 0.f;
#pragma unroll
    for (int m = 0; m < MVV; m++) {
        float e = __expf(z[m] - mx);
        se += e;
        sw += e * sBeta[m];
    }
    attn[(size_t)b * VV + v] = sw / se;
}

// ---------------- beta[b,mv] = tanh(vn[b,mv,:] . bw + bb) * exp(0.01*(MV-mv)) ----------------
__global__ void beta_kernel(const float* __restrict__ vn, const float* __restrict__ bw,
                            const float* __restrict__ bb, float* __restrict__ beta, int BMV)
{
    int gw = (blockIdx.x * blockDim.x + threadIdx.x) >> 5;
    int lane = threadIdx.x & 31;
    if (gw >= BMV) return;
    int mv = gw % MVV;
    const float* row = vn + (size_t)gw * VV;
    float s = 0.f;
    for (int k = lane; k < VV; k += 32) s = fmaf(row[k], bw[k], s);
#pragma unroll
    for (int o = 16; o > 0; o >>= 1) s += __shfl_xor_sync(0xffffffffu, s, o);
    if (lane == 0) beta[gw] = tanhf(s + bb[0]) * __expf(0.01f * (float)(MVV - mv));
}

// ---------------- generic out[r,c] = act( (a1[r,:] + s*a2[r,:]) @ w[c,:] + bias[c] ), K=N=128 ----------------
__global__ __launch_bounds__(256) void gemm128_kernel(
    const float* __restrict__ a1, const float* __restrict__ a2,
    const float* __restrict__ epsp, int layer,
    const float* __restrict__ w, const float* __restrict__ bias,
    float* __restrict__ out, int M, int relu)
{
    __shared__ float sIn[128][33];
    __shared__ float sW[128][33];
    const int tid = threadIdx.x;
    const int rg = tid >> 4, cg = tid & 15;
    const int rbase = blockIdx.x * 128;
    float scale = 0.f;
    if (a2) scale = 1.0f + epsp[layer];

    float acc[8][8];
#pragma unroll
    for (int i = 0; i < 8; i++)
#pragma unroll
        for (int j = 0; j < 8; j++) acc[i][j] = 0.f;

    for (int k0 = 0; k0 < 128; k0 += 32) {
#pragma unroll
        for (int f = tid; f < 1024; f += 256) {
            int row = f >> 3, c4 = f & 7;
            int r = rbase + row;
            float4 v = make_float4(0.f, 0.f, 0.f, 0.f);
            if (r < M) {
                v = *reinterpret_cast<const float4*>(a1 + (size_t)r * 128 + k0 + c4 * 4);
                if (a2) {
                    float4 u = *reinterpret_cast<const float4*>(a2 + (size_t)r * 128 + k0 + c4 * 4);
                    v.x = fmaf(scale, u.x, v.x); v.y = fmaf(scale, u.y, v.y);
                    v.z = fmaf(scale, u.z, v.z); v.w = fmaf(scale, u.w, v.w);
                }
            }
            float* p = &sIn[row][c4 * 4];
            p[0] = v.x; p[1] = v.y; p[2] = v.z; p[3] = v.w;
        }
#pragma unroll
        for (int f = tid; f < 1024; f += 256) {
            int row = f >> 3, c4 = f & 7;
            float4 v = *reinterpret_cast<const float4*>(w + (size_t)row * 128 + k0 + c4 * 4);
            float* p = &sW[row][c4 * 4];
            p[0] = v.x; p[1] = v.y; p[2] = v.z; p[3] = v.w;
        }
        __syncthreads();
#pragma unroll 4
        for (int k = 0; k < 32; k++) {
            float aa[8], bb[8];
#pragma unroll
            for (int i = 0; i < 8; i++) aa[i] = sIn[rg + 16 * i][k];
#pragma unroll
            for (int i = 0; i < 8; i++) bb[i] = sW[cg + 16 * i][k];
#pragma unroll
            for (int i = 0; i < 8; i++)
#pragma unroll
                for (int j = 0; j < 8; j++) acc[i][j] = fmaf(aa[i], bb[j], acc[i][j]);
        }
        __syncthreads();
    }
#pragma unroll
    for (int i = 0; i < 8; i++) {
        int r = rbase + rg + 16 * i;
        if (r >= M) continue;
#pragma unroll
        for (int j = 0; j < 8; j++) {
            int c = cg + 16 * j;
            float v = acc[i][j] + bias[c];
            if (relu) v = fmaxf(v, 0.f);
            out[(size_t)r * 128 + c] = v;
        }
    }
}

// ---------------- relmsg[t,:] = (edge_lin[t,:] . wrw + wrb) * edge_lin[t,:] ----------------
__global__ void relmsg_kernel(const float* __restrict__ el, const float* __restrict__ wrw,
                              const float* __restrict__ wrb, float* __restrict__ rm)
{
    int t = blockIdx.x, tid = threadIdx.x;  // 128 threads
    __shared__ float warpred[4];
    __shared__ float wsh;
    float v = el[(size_t)t * HH + tid];
    float p = v * wrw[tid];
#pragma unroll
    for (int o = 16; o > 0; o >>= 1) p += __shfl_xor_sync(0xffffffffu, p, o);
    if ((tid & 31) == 0) warpred[tid >> 5] = p;
    __syncthreads();
    if (tid == 0) wsh = warpred[0] + warpred[1] + warpred[2] + warpred[3] + wrb[0];
    __syncthreads();
    rm[(size_t)t * HH + tid] = wsh * v;
}

// ---------------- x0 gather: x[i,:] = node_lin[node_ids[i],:] ----------------
__global__ void gather_kernel(const int* __restrict__ nids, const float* __restrict__ nl,
                              float* __restrict__ x, int n)
{
    int gt = blockIdx.x * blockDim.x + threadIdx.x;
    int i = gt >> 5;
    if (i >= n) return;
    int lane = gt & 31;
    *reinterpret_cast<float4*>(x + (size_t)i * HH + lane * 4) =
        *reinterpret_cast<const float4*>(nl + (size_t)__ldg(nids + i) * HH + lane * 4);
}

// ---------------- edge message + scatter: agg[dst] += relu(a*x[src] + relmsg[type]) ----------------
__global__ void msg_kernel(const int* __restrict__ ei, const int* __restrict__ eids,
                           const int* __restrict__ nids, const int* __restrict__ batch,
                           const float* __restrict__ attn, const float* __restrict__ x,
                           const float* __restrict__ relmsg, float* __restrict__ agg, int E)
{
    int gt = blockIdx.x * blockDim.x + threadIdx.x;
    int e = gt >> 5;
    if (e >= E) return;
    int lane = gt & 31;
    int src = __ldg(ei + e);
    int dst = __ldg(ei + E + e);
    int t = __ldg(eids + e);
    float a = __ldg(attn + (size_t)__ldg(batch + src) * VV + __ldg(nids + src));
    float4 xv = *reinterpret_cast<const float4*>(x + (size_t)src * HH + lane * 4);
    float4 rm = __ldg(reinterpret_cast<const float4*>(relmsg + (size_t)t * HH + lane * 4));
    float m0 = fmaxf(fmaf(a, xv.x, rm.x), 0.f);
    float m1 = fmaxf(fmaf(a, xv.y, rm.y), 0.f);
    float m2 = fmaxf(fmaf(a, xv.z, rm.z), 0.f);
    float m3 = fmaxf(fmaf(a, xv.w, rm.w), 0.f);
    float* p = agg + (size_t)dst * HH + lane * 4;
    asm volatile("red.global.add.v4.f32 [%0], {%1,%2,%3,%4};"
                 :: "l"(p), "f"(m0), "f"(m1), "f"(m2), "f"(m3) : "memory");
}

// ---------------- mean-pool accumulation ----------------
__global__ void pool_kernel(const int* __restrict__ batch, const float* __restrict__ x,
                            float* __restrict__ pooled, float* __restrict__ cnt, int n)
{
    int gt = blockIdx.x * blockDim.x + threadIdx.x;
    int i = gt >> 5;
    if (i >= n) return;
    int lane = gt & 31;
    int b = __ldg(batch + i);
    float4 v = *reinterpret_cast<const float4*>(x + (size_t)i * HH + lane * 4);
    float* p = pooled + (size_t)b * HH + lane * 4;
    asm volatile("red.global.add.v4.f32 [%0], {%1,%2,%3,%4};"
                 :: "l"(p), "f"(v.x), "f"(v.y), "f"(v.z), "f"(v.w) : "memory");
    if (lane == 0) atomicAdd(cnt + b, 1.0f);
}

// ---------------- per-graph head: mean pool, node branch, MLP ----------------
__global__ __launch_bounds__(128) void final_kernel(
    const float* __restrict__ ehr, const float* __restrict__ nemb,
    const float* __restrict__ lw, const float* __restrict__ lb,
    const float* __restrict__ pooled, const float* __restrict__ cnt,
    const float* __restrict__ mw, const float* __restrict__ mb,
    float* __restrict__ out)
{
    int b = blockIdx.x, tid = threadIdx.x;
    __shared__ float sE[128];
    __shared__ float cat[256];
    __shared__ float red4[4];
    __shared__ float sSum;
    const float* eb = ehr + (size_t)b * VV;

    float s = 0.f;
    for (int v = tid; v < VV; v += 128) s += eb[v];
#pragma unroll
    for (int o = 16; o > 0; o >>= 1) s += __shfl_xor_sync(0xffffffffu, s, o);
    if ((tid & 31) == 0) red4[tid >> 5] = s;
    __syncthreads();
    if (tid == 0) sSum = red4[0] + red4[1] + red4[2] + red4[3];
    __syncthreads();

    float accd = 0.f;
    for (int v0 = 0; v0 < VV; v0 += 128) {
        __syncthreads();
        sE[tid] = eb[v0 + tid];
        __syncthreads();
#pragma unroll 8
        for (int vv = 0; vv < 128; vv++)
            accd = fmaf(sE[vv], nemb[(size_t)(v0 + vv) * HH + tid], accd);
    }
    accd /= sSum;
    __syncthreads();
    sE[tid] = accd;
    __syncthreads();

    float xl = lb[tid];
#pragma unroll 8
    for (int d = 0; d < 128; d++) xl = fmaf(sE[d], lw[(size_t)tid * 128 + d], xl);
    cat[128 + tid] = xl;
    float c = fmaxf(cnt[b], 1.0f);
    cat[tid] = pooled[(size_t)b * HH + tid] / c;
    __syncthreads();
    if (tid < 25) {
        float o = mb[tid];
#pragma unroll 8
        for (int j = 0; j < 256; j++) o = fmaf(cat[j], mw[(size_t)tid * 256 + j], o);
        out[b * 25 + tid] = o;
    }
}

// ---------------- launch ----------------
extern "C" void kernel_launch(void* const* d_in, const int* in_sizes, int n_in,
                              void* d_out, int out_size)
{
    const int*   node_ids   = (const int*)d_in[0];
    const int*   edge_ids   = (const int*)d_in[1];
    const int*   edge_index = (const int*)d_in[2];
    const float* visit_node = (const float*)d_in[6];
    const float* ehr        = (const float*)d_in[7];
    const int*   batch      = (const int*)d_in[8];
    const float* node_emb   = (const float*)d_in[10];
    const float* edge_emb   = (const float*)d_in[11];
    const float* lin_w      = (const float*)d_in[12];
    const float* lin_b      = (const float*)d_in[13];
    const float* alpha_w    = (const float*)d_in[14];
    const float* beta_w     = (const float*)d_in[16];
    const float* beta_b     = (const float*)d_in[17];
    const float* conv_w     = (const float*)d_in[18];
    const float* conv_b     = (const float*)d_in[19];
    const float* wr_w       = (const float*)d_in[20];
    const float* wr_b       = (const float*)d_in[21];
    const float* epsp       = (const float*)d_in[22];
    const float* mlp_w      = (const float*)d_in[23];
    const float* mlp_b      = (const float*)d_in[24];

    const int N = in_sizes[0];
    const int E = in_sizes[1];
    const int B = in_sizes[7] / VV;
    const int NT = in_sizes[11] / HH;  // edge-type count (500)

    float *xA, *xB, *nl, *elin, *rm, *attn, *beta, *pooled, *cnt, *logits;
    cudaGetSymbolAddress((void**)&xA, g_xA);
    cudaGetSymbolAddress((void**)&xB, g_xB);
    cudaGetSymbolAddress((void**)&nl, g_node_lin);
    cudaGetSymbolAddress((void**)&elin, g_edge_lin);
    cudaGetSymbolAddress((void**)&rm, g_relmsg);
    cudaGetSymbolAddress((void**)&attn, g_attn);
    cudaGetSymbolAddress((void**)&beta, g_beta);
    cudaGetSymbolAddress((void**)&pooled, g_pooled);
    cudaGetSymbolAddress((void**)&cnt, g_cnt);
    cudaGetSymbolAddress((void**)&logits, g_logits);

    // vocabulary-level precompute (4096 + 500 rows instead of 50000 + 800000)
    gemm128_kernel<<<(VV + 127) / 128, 256>>>(node_emb, nullptr, nullptr, 0, lin_w, lin_b, nl, VV, 0);
    gemm128_kernel<<<(NT + 127) / 128, 256>>>(edge_emb, nullptr, nullptr, 0, lin_w, lin_b, elin, NT, 0);
    gather_kernel<<<(N * 32 + 255) / 256, 256>>>(node_ids, nl, xA, N);

    const int Mrows = B * MVV;  // 1280
    for (int l = 0; l < 2; l++) {
        float* xcur = (l == 0) ? xA : xB;
        float* aggb = (l == 0) ? xB : xA;
        beta_kernel<<<(B * MVV * 32 + 255) / 256, 256>>>(visit_node, beta_w + (size_t)l * VV,
                                                         beta_b + l, beta, B * MVV);
        tf32_gemm_kernel<<<dim3(VV / 128, Mrows / 128), 256>>>(
            visit_node, alpha_w + (size_t)l * VV * VV, logits);
        softmax_beta_kernel<<<dim3(VV / 256, B), 256>>>(logits, beta, attn);
        relmsg_kernel<<<NT, 128>>>(elin, wr_w + (size_t)l * HH, wr_b + l, rm);
        cudaMemsetAsync(aggb, 0, (size_t)N * HH * sizeof(float));
        msg_kernel<<<(E * 32 + 255) / 256, 256>>>(edge_index, edge_ids, node_ids, batch,
                                                  attn, xcur, rm, aggb, E);
        // in-place: each block only reads/writes its own 128 rows, writes after all reads
        gemm128_kernel<<<(N + 127) / 128, 256>>>(aggb, xcur, epsp, l,
                                                 conv_w + (size_t)l * HH * HH, conv_b + (size_t)l * HH,
                                                 aggb, N, 1);
    }

    cudaMemsetAsync(pooled, 0, (size_t)BMAX * HH * sizeof(float));
    cudaMemsetAsync(cnt, 0, BMAX * sizeof(float));
    pool_kernel<<<(N * 32 + 255) / 256, 256>>>(batch, xA, pooled, cnt, N);
    final_kernel<<<B, 128>>>(ehr, node_emb, lin_w, lin_b, pooled, cnt, mlp_w, mlp_b, (float*)d_out);
}

// round 5
// speedup vs baseline: 1.3774x; 1.3774x over previous
#include <cuda_runtime.h>
#include <cuda_bf16.h>
#include <cstdint>

#define VV 4096
#define HH 128
#define MVV 20
#define NMAX 50000
#define ETYPES_MAX 512
#define BMAX 64

// ---------------- static scratch (no runtime allocation allowed) ----------------
__device__ __align__(16) float g_xA[(size_t)NMAX * HH];
__device__ __align__(16) float g_xB[(size_t)NMAX * HH];
__device__ __align__(16) float g_node_lin[VV * HH];
__device__ __align__(16) float g_edge_lin[ETYPES_MAX * HH];
__device__ __align__(16) float g_relmsg[ETYPES_MAX * HH];
__device__ __align__(16) float g_attn[BMAX * VV];
__device__ float g_beta[BMAX * MVV];
__device__ __align__(16) float g_pooled[BMAX * HH];
__device__ float g_cnt[BMAX];
__device__ __align__(16) float g_logits[(size_t)BMAX * MVV * VV];            // 21 MB
__device__ __align__(16) __nv_bfloat16 g_A16[(size_t)BMAX * MVV * VV];       // 10.5 MB
__device__ __align__(16) __nv_bfloat16 g_B16[(size_t)2 * VV * VV];           // 67 MB

// ---------------- fp32 -> bf16 bulk convert (vectorized, bandwidth-bound) ----------------
__global__ void f2bf_kernel(const float4* __restrict__ src, uint2* __restrict__ dst, int n4)
{
    int i = blockIdx.x * blockDim.x + threadIdx.x;
    if (i >= n4) return;
    float4 v = src[i];
    __nv_bfloat162 lo, hi;
    lo.x = __float2bfloat16(v.x); lo.y = __float2bfloat16(v.y);
    hi.x = __float2bfloat16(v.z); hi.y = __float2bfloat16(v.w);
    uint2 o;
    o.x = *reinterpret_cast<uint32_t*>(&lo);
    o.y = *reinterpret_cast<uint32_t*>(&hi);
    dst[i] = o;
}

// ================= bf16 tensor-core GEMM: C[r,c] = sum_k A[r,k]*B[c,k] =================
// A: [M][4096] bf16 row-major, B: [4096][4096] bf16 row-major (both pre-converted).
// block tile 128x128, k-step 32, 8 warps (2x4), warp tile 64x32, mma m16n8k16.
// smem: bf16-pair words, row stride 20 words -> fragment reads (gid*20+tig)%32 is a
// perfect bank permutation (conflict-free).
__global__ __launch_bounds__(256) void bf16_gemm_kernel(
    const __nv_bfloat16* __restrict__ A, const __nv_bfloat16* __restrict__ Bm,
    float* __restrict__ C)
{
    __shared__ uint32_t sA[128][20];
    __shared__ uint32_t sB[128][20];

    const int tid = threadIdx.x;
    const int warpId = tid >> 5, lane = tid & 31;
    const int wr = warpId >> 2, wc = warpId & 3;
    const int gid = lane >> 2, tig = lane & 3;
    const int rbase = blockIdx.y * 128;
    const int cbase = blockIdx.x * 128;

    const int lrow = tid >> 1;          // 0..127
    const int lhalf = tid & 1;          // 16-element half of the 32-wide k-slice

    const __nv_bfloat16* Ap = A + (size_t)(rbase + lrow) * VV + lhalf * 16;
    const __nv_bfloat16* Bp = Bm + (size_t)(cbase + lrow) * VV + lhalf * 16;

    uint4 ra[2], rb[2];
    float acc[4][4][4];
#pragma unroll
    for (int i = 0; i < 4; i++)
#pragma unroll
        for (int j = 0; j < 4; j++)
#pragma unroll
            for (int q = 0; q < 4; q++) acc[i][j][q] = 0.f;

    ra[0] = *reinterpret_cast<const uint4*>(Ap);
    ra[1] = *reinterpret_cast<const uint4*>(Ap + 8);
    rb[0] = *reinterpret_cast<const uint4*>(Bp);
    rb[1] = *reinterpret_cast<const uint4*>(Bp + 8);

    for (int kt = 0; kt < VV / 32; kt++) {
        uint32_t* pa = &sA[lrow][lhalf * 8];
        pa[0] = ra[0].x; pa[1] = ra[0].y; pa[2] = ra[0].z; pa[3] = ra[0].w;
        pa[4] = ra[1].x; pa[5] = ra[1].y; pa[6] = ra[1].z; pa[7] = ra[1].w;
        uint32_t* pb = &sB[lrow][lhalf * 8];
        pb[0] = rb[0].x; pb[1] = rb[0].y; pb[2] = rb[0].z; pb[3] = rb[0].w;
        pb[4] = rb[1].x; pb[5] = rb[1].y; pb[6] = rb[1].z; pb[7] = rb[1].w;
        __syncthreads();

        if (kt + 1 < VV / 32) {
            const __nv_bfloat16* An = Ap + (size_t)(kt + 1) * 32;
            const __nv_bfloat16* Bn = Bp + (size_t)(kt + 1) * 32;
            ra[0] = *reinterpret_cast<const uint4*>(An);
            ra[1] = *reinterpret_cast<const uint4*>(An + 8);
            rb[0] = *reinterpret_cast<const uint4*>(Bn);
            rb[1] = *reinterpret_cast<const uint4*>(Bn + 8);
        }

#pragma unroll
        for (int ks = 0; ks < 2; ks++) {
            const int k8 = ks * 8;
            uint32_t af[4][4], bf[4][2];
#pragma unroll
            for (int mf = 0; mf < 4; mf++) {
                int r0 = wr * 64 + mf * 16 + gid;
                af[mf][0] = sA[r0][k8 + tig];
                af[mf][1] = sA[r0 + 8][k8 + tig];
                af[mf][2] = sA[r0][k8 + tig + 4];
                af[mf][3] = sA[r0 + 8][k8 + tig + 4];
            }
#pragma unroll
            for (int nf = 0; nf < 4; nf++) {
                int c0 = wc * 32 + nf * 8 + gid;
                bf[nf][0] = sB[c0][k8 + tig];
                bf[nf][1] = sB[c0][k8 + tig + 4];
            }
#pragma unroll
            for (int mf = 0; mf < 4; mf++)
#pragma unroll
                for (int nf = 0; nf < 4; nf++) {
                    asm volatile(
                        "mma.sync.aligned.m16n8k16.row.col.f32.bf16.bf16.f32 "
                        "{%0,%1,%2,%3}, {%4,%5,%6,%7}, {%8,%9}, {%0,%1,%2,%3};"
                        : "+f"(acc[mf][nf][0]), "+f"(acc[mf][nf][1]),
                          "+f"(acc[mf][nf][2]), "+f"(acc[mf][nf][3])
                        : "r"(af[mf][0]), "r"(af[mf][1]), "r"(af[mf][2]), "r"(af[mf][3]),
                          "r"(bf[nf][0]), "r"(bf[nf][1]));
                }
        }
        __syncthreads();
    }

#pragma unroll
    for (int mf = 0; mf < 4; mf++) {
        int r0 = rbase + wr * 64 + mf * 16 + gid;
#pragma unroll
        for (int nf = 0; nf < 4; nf++) {
            int c0 = cbase + wc * 32 + nf * 8 + tig * 2;
            *reinterpret_cast<float2*>(C + (size_t)r0 * VV + c0) =
                make_float2(acc[mf][nf][0], acc[mf][nf][1]);
            *reinterpret_cast<float2*>(C + (size_t)(r0 + 8) * VV + c0) =
                make_float2(acc[mf][nf][2], acc[mf][nf][3]);
        }
    }
}

// ---------------- softmax over MV + beta reduce: attn[b,v] ----------------
__global__ __launch_bounds__(256) void softmax_beta_kernel(
    const float* __restrict__ logits, const float* __restrict__ beta,
    float* __restrict__ attn)
{
    __shared__ float sBeta[MVV];
    const int b = blockIdx.y;
    const int v = blockIdx.x * 256 + threadIdx.x;
    if (threadIdx.x < MVV) sBeta[threadIdx.x] = beta[b * MVV + threadIdx.x];
    __syncthreads();
    const float* lp = logits + (size_t)b * MVV * VV + v;
    float z[MVV];
    float mx = -1e30f;
#pragma unroll
    for (int m = 0; m < MVV; m++) {
        z[m] = lp[(size_t)m * VV];
        mx = fmaxf(mx, z[m]);
    }
    float se = 0.f, sw = 0.f;
#pragma unroll
    for (int m = 0; m < MVV; m++) {
        float e = __expf(z[m] - mx);
        se += e;
        sw += e * sBeta[m];
    }
    attn[(size_t)b * VV + v] = sw / se;
}

// ---------------- beta[b,mv] = tanh(vn[b,mv,:] . bw + bb) * exp(0.01*(MV-mv)) ----------------
__global__ void beta_kernel(const float* __restrict__ vn, const float* __restrict__ bw,
                            const float* __restrict__ bb, float* __restrict__ beta, int BMV)
{
    int gw = (blockIdx.x * blockDim.x + threadIdx.x) >> 5;
    int lane = threadIdx.x & 31;
    if (gw >= BMV) return;
    int mv = gw % MVV;
    const float* row = vn + (size_t)gw * VV;
    float s = 0.f;
    for (int k = lane; k < VV; k += 32) s = fmaf(row[k], bw[k], s);
#pragma unroll
    for (int o = 16; o > 0; o >>= 1) s += __shfl_xor_sync(0xffffffffu, s, o);
    if (lane == 0) beta[gw] = tanhf(s + bb[0]) * __expf(0.01f * (float)(MVV - mv));
}

// ---------------- generic out[r,c] = act( (a1[r,:] + s*a2[r,:]) @ w[c,:] + bias[c] ), K=N=128 ----------------
__global__ __launch_bounds__(256) void gemm128_kernel(
    const float* __restrict__ a1, const float* __restrict__ a2,
    const float* __restrict__ epsp, int layer,
    const float* __restrict__ w, const float* __restrict__ bias,
    float* __restrict__ out, int M, int relu)
{
    __shared__ float sIn[128][33];
    __shared__ float sW[128][33];
    const int tid = threadIdx.x;
    const int rg = tid >> 4, cg = tid & 15;
    const int rbase = blockIdx.x * 128;
    float scale = 0.f;
    if (a2) scale = 1.0f + epsp[layer];

    float acc[8][8];
#pragma unroll
    for (int i = 0; i < 8; i++)
#pragma unroll
        for (int j = 0; j < 8; j++) acc[i][j] = 0.f;

    for (int k0 = 0; k0 < 128; k0 += 32) {
#pragma unroll
        for (int f = tid; f < 1024; f += 256) {
            int row = f >> 3, c4 = f & 7;
            int r = rbase + row;
            float4 v = make_float4(0.f, 0.f, 0.f, 0.f);
            if (r < M) {
                v = *reinterpret_cast<const float4*>(a1 + (size_t)r * 128 + k0 + c4 * 4);
                if (a2) {
                    float4 u = *reinterpret_cast<const float4*>(a2 + (size_t)r * 128 + k0 + c4 * 4);
                    v.x = fmaf(scale, u.x, v.x); v.y = fmaf(scale, u.y, v.y);
                    v.z = fmaf(scale, u.z, v.z); v.w = fmaf(scale, u.w, v.w);
                }
            }
            float* p = &sIn[row][c4 * 4];
            p[0] = v.x; p[1] = v.y; p[2] = v.z; p[3] = v.w;
        }
#pragma unroll
        for (int f = tid; f < 1024; f += 256) {
            int row = f >> 3, c4 = f & 7;
            float4 v = *reinterpret_cast<const float4*>(w + (size_t)row * 128 + k0 + c4 * 4);
            float* p = &sW[row][c4 * 4];
            p[0] = v.x; p[1] = v.y; p[2] = v.z; p[3] = v.w;
        }
        __syncthreads();
#pragma unroll 4
        for (int k = 0; k < 32; k++) {
            float aa[8], bb[8];
#pragma unroll
            for (int i = 0; i < 8; i++) aa[i] = sIn[rg + 16 * i][k];
#pragma unroll
            for (int i = 0; i < 8; i++) bb[i] = sW[cg + 16 * i][k];
#pragma unroll
            for (int i = 0; i < 8; i++)
#pragma unroll
                for (int j = 0; j < 8; j++) acc[i][j] = fmaf(aa[i], bb[j], acc[i][j]);
        }
        __syncthreads();
    }
#pragma unroll
    for (int i = 0; i < 8; i++) {
        int r = rbase + rg + 16 * i;
        if (r >= M) continue;
#pragma unroll
        for (int j = 0; j < 8; j++) {
            int c = cg + 16 * j;
            float v = acc[i][j] + bias[c];
            if (relu) v = fmaxf(v, 0.f);
            out[(size_t)r * 128 + c] = v;
        }
    }
}

// ---------------- relmsg[t,:] = (edge_lin[t,:] . wrw + wrb) * edge_lin[t,:] ----------------
__global__ void relmsg_kernel(const float* __restrict__ el, const float* __restrict__ wrw,
                              const float* __restrict__ wrb, float* __restrict__ rm)
{
    int t = blockIdx.x, tid = threadIdx.x;  // 128 threads
    __shared__ float warpred[4];
    __shared__ float wsh;
    float v = el[(size_t)t * HH + tid];
    float p = v * wrw[tid];
#pragma unroll
    for (int o = 16; o > 0; o >>= 1) p += __shfl_xor_sync(0xffffffffu, p, o);
    if ((tid & 31) == 0) warpred[tid >> 5] = p;
    __syncthreads();
    if (tid == 0) wsh = warpred[0] + warpred[1] + warpred[2] + warpred[3] + wrb[0];
    __syncthreads();
    rm[(size_t)t * HH + tid] = wsh * v;
}

// ---------------- x0 gather: x[i,:] = node_lin[node_ids[i],:] ----------------
__global__ void gather_kernel(const int* __restrict__ nids, const float* __restrict__ nl,
                              float* __restrict__ x, int n)
{
    int gt = blockIdx.x * blockDim.x + threadIdx.x;
    int i = gt >> 5;
    if (i >= n) return;
    int lane = gt & 31;
    *reinterpret_cast<float4*>(x + (size_t)i * HH + lane * 4) =
        *reinterpret_cast<const float4*>(nl + (size_t)__ldg(nids + i) * HH + lane * 4);
}

// ---------------- edge message + scatter: agg[dst] += relu(a*x[src] + relmsg[type]) ----------------
__global__ void msg_kernel(const int* __restrict__ ei, const int* __restrict__ eids,
                           const int* __restrict__ nids, const int* __restrict__ batch,
                           const float* __restrict__ attn, const float* __restrict__ x,
                           const float* __restrict__ relmsg, float* __restrict__ agg, int E)
{
    int gt = blockIdx.x * blockDim.x + threadIdx.x;
    int e = gt >> 5;
    if (e >= E) return;
    int lane = gt & 31;
    int src = __ldg(ei + e);
    int dst = __ldg(ei + E + e);
    int t = __ldg(eids + e);
    float a = __ldg(attn + (size_t)__ldg(batch + src) * VV + __ldg(nids + src));
    float4 xv = *reinterpret_cast<const float4*>(x + (size_t)src * HH + lane * 4);
    float4 rm = __ldg(reinterpret_cast<const float4*>(relmsg + (size_t)t * HH + lane * 4));
    float m0 = fmaxf(fmaf(a, xv.x, rm.x), 0.f);
    float m1 = fmaxf(fmaf(a, xv.y, rm.y), 0.f);
    float m2 = fmaxf(fmaf(a, xv.z, rm.z), 0.f);
    float m3 = fmaxf(fmaf(a, xv.w, rm.w), 0.f);
    float* p = agg + (size_t)dst * HH + lane * 4;
    asm volatile("red.global.add.v4.f32 [%0], {%1,%2,%3,%4};"
                 :: "l"(p), "f"(m0), "f"(m1), "f"(m2), "f"(m3) : "memory");
}

// ---------------- mean-pool accumulation ----------------
__global__ void pool_kernel(const int* __restrict__ batch, const float* __restrict__ x,
                            float* __restrict__ pooled, float* __restrict__ cnt, int n)
{
    int gt = blockIdx.x * blockDim.x + threadIdx.x;
    int i = gt >> 5;
    if (i >= n) return;
    int lane = gt & 31;
    int b = __ldg(batch + i);
    float4 v = *reinterpret_cast<const float4*>(x + (size_t)i * HH + lane * 4);
    float* p = pooled + (size_t)b * HH + lane * 4;
    asm volatile("red.global.add.v4.f32 [%0], {%1,%2,%3,%4};"
                 :: "l"(p), "f"(v.x), "f"(v.y), "f"(v.z), "f"(v.w) : "memory");
    if (lane == 0) atomicAdd(cnt + b, 1.0f);
}

// ---------------- per-graph head: mean pool, node branch, MLP ----------------
__global__ __launch_bounds__(128) void final_kernel(
    const float* __restrict__ ehr, const float* __restrict__ nemb,
    const float* __restrict__ lw, const float* __restrict__ lb,
    const float* __restrict__ pooled, const float* __restrict__ cnt,
    const float* __restrict__ mw, const float* __restrict__ mb,
    float* __restrict__ out)
{
    int b = blockIdx.x, tid = threadIdx.x;
    __shared__ float sE[128];
    __shared__ float cat[256];
    __shared__ float red4[4];
    __shared__ float sSum;
    const float* eb = ehr + (size_t)b * VV;

    float s = 0.f;
    for (int v = tid; v < VV; v += 128) s += eb[v];
#pragma unroll
    for (int o = 16; o > 0; o >>= 1) s += __shfl_xor_sync(0xffffffffu, s, o);
    if ((tid & 31) == 0) red4[tid >> 5] = s;
    __syncthreads();
    if (tid == 0) sSum = red4[0] + red4[1] + red4[2] + red4[3];
    __syncthreads();

    float accd = 0.f;
    for (int v0 = 0; v0 < VV; v0 += 128) {
        __syncthreads();
        sE[tid] = eb[v0 + tid];
        __syncthreads();
#pragma unroll 8
        for (int vv = 0; vv < 128; vv++)
            accd = fmaf(sE[vv], nemb[(size_t)(v0 + vv) * HH + tid], accd);
    }
    accd /= sSum;
    __syncthreads();
    sE[tid] = accd;
    __syncthreads();

    float xl = lb[tid];
#pragma unroll 8
    for (int d = 0; d < 128; d++) xl = fmaf(sE[d], lw[(size_t)tid * 128 + d], xl);
    cat[128 + tid] = xl;
    float c = fmaxf(cnt[b], 1.0f);
    cat[tid] = pooled[(size_t)b * HH + tid] / c;
    __syncthreads();
    if (tid < 25) {
        float o = mb[tid];
#pragma unroll 8
        for (int j = 0; j < 256; j++) o = fmaf(cat[j], mw[(size_t)tid * 256 + j], o);
        out[b * 25 + tid] = o;
    }
}

// ---------------- launch ----------------
extern "C" void kernel_launch(void* const* d_in, const int* in_sizes, int n_in,
                              void* d_out, int out_size)
{
    const int*   node_ids   = (const int*)d_in[0];
    const int*   edge_ids   = (const int*)d_in[1];
    const int*   edge_index = (const int*)d_in[2];
    const float* visit_node = (const float*)d_in[6];
    const float* ehr        = (const float*)d_in[7];
    const int*   batch      = (const int*)d_in[8];
    const float* node_emb   = (const float*)d_in[10];
    const float* edge_emb   = (const float*)d_in[11];
    const float* lin_w      = (const float*)d_in[12];
    const float* lin_b      = (const float*)d_in[13];
    const float* alpha_w    = (const float*)d_in[14];
    const float* beta_w     = (const float*)d_in[16];
    const float* beta_b     = (const float*)d_in[17];
    const float* conv_w     = (const float*)d_in[18];
    const float* conv_b     = (const float*)d_in[19];
    const float* wr_w       = (const float*)d_in[20];
    const float* wr_b       = (const float*)d_in[21];
    const float* epsp       = (const float*)d_in[22];
    const float* mlp_w      = (const float*)d_in[23];
    const float* mlp_b      = (const float*)d_in[24];

    const int N = in_sizes[0];
    const int E = in_sizes[1];
    const int B = in_sizes[7] / VV;
    const int NT = in_sizes[11] / HH;  // edge-type count (500)
    const int AW = in_sizes[14];       // 2*4096*4096
    const int VN = in_sizes[6];        // B*MV*4096

    float *xA, *xB, *nl, *elin, *rm, *attn, *beta, *pooled, *cnt, *logits;
    __nv_bfloat16 *A16, *B16;
    cudaGetSymbolAddress((void**)&xA, g_xA);
    cudaGetSymbolAddress((void**)&xB, g_xB);
    cudaGetSymbolAddress((void**)&nl, g_node_lin);
    cudaGetSymbolAddress((void**)&elin, g_edge_lin);
    cudaGetSymbolAddress((void**)&rm, g_relmsg);
    cudaGetSymbolAddress((void**)&attn, g_attn);
    cudaGetSymbolAddress((void**)&beta, g_beta);
    cudaGetSymbolAddress((void**)&pooled, g_pooled);
    cudaGetSymbolAddress((void**)&cnt, g_cnt);
    cudaGetSymbolAddress((void**)&logits, g_logits);
    cudaGetSymbolAddress((void**)&A16, g_A16);
    cudaGetSymbolAddress((void**)&B16, g_B16);

    // one-time bf16 conversions (bandwidth-bound)
    f2bf_kernel<<<(VN / 4 + 255) / 256, 256>>>(
        (const float4*)visit_node, (uint2*)A16, VN / 4);
    f2bf_kernel<<<(AW / 4 + 255) / 256, 256>>>(
        (const float4*)alpha_w, (uint2*)B16, AW / 4);

    // vocabulary-level precompute (4096 + 500 rows instead of 50000 + 800000)
    gemm128_kernel<<<(VV + 127) / 128, 256>>>(node_emb, nullptr, nullptr, 0, lin_w, lin_b, nl, VV, 0);
    gemm128_kernel<<<(NT + 127) / 128, 256>>>(edge_emb, nullptr, nullptr, 0, lin_w, lin_b, elin, NT, 0);
    gather_kernel<<<(N * 32 + 255) / 256, 256>>>(node_ids, nl, xA, N);

    const int Mrows = B * MVV;  // 1280
    for (int l = 0; l < 2; l++) {
        float* xcur = (l == 0) ? xA : xB;
        float* aggb = (l == 0) ? xB : xA;
        beta_kernel<<<(B * MVV * 32 + 255) / 256, 256>>>(visit_node, beta_w + (size_t)l * VV,
                                                         beta_b + l, beta, B * MVV);
        bf16_gemm_kernel<<<dim3(VV / 128, Mrows / 128), 256>>>(
            A16, B16 + (size_t)l * VV * VV, logits);
        softmax_beta_kernel<<<dim3(VV / 256, B), 256>>>(logits, beta, attn);
        relmsg_kernel<<<NT, 128>>>(elin, wr_w + (size_t)l * HH, wr_b + l, rm);
        cudaMemsetAsync(aggb, 0, (size_t)N * HH * sizeof(float));
        msg_kernel<<<(E * 32 + 255) / 256, 256>>>(edge_index, edge_ids, node_ids, batch,
                                                  attn, xcur, rm, aggb, E);
        // in-place: each block only reads/writes its own 128 rows, writes after all reads
        gemm128_kernel<<<(N + 127) / 128, 256>>>(aggb, xcur, epsp, l,
                                                 conv_w + (size_t)l * HH * HH, conv_b + (size_t)l * HH,
                                                 aggb, N, 1);
    }

    cudaMemsetAsync(pooled, 0, (size_t)BMAX * HH * sizeof(float));
    cudaMemsetAsync(cnt, 0, BMAX * sizeof(float));
    pool_kernel<<<(N * 32 + 255) / 256, 256>>>(batch, xA, pooled, cnt, N);
    final_kernel<<<B, 128>>>(ehr, node_emb, lin_w, lin_b, pooled, cnt, mlp_w, mlp_b, (float*)d_out);
}

// round 7
// speedup vs baseline: 2.0264x; 1.4712x over previous
#include <cuda_runtime.h>
#include <cuda_bf16.h>
#include <cstdint>

#define VV 4096
#define HH 128
#define MVV 20
#define NMAX 50000
#define ETYPES_MAX 512
#define BMAX 64
#define MROWS (BMAX * MVV)   // 1280

// ---------------- static scratch (no runtime allocation allowed) ----------------
__device__ __align__(16) float g_xA[(size_t)NMAX * HH];
__device__ __align__(16) float g_xB[(size_t)NMAX * HH];
__device__ __align__(16) float g_node_lin[VV * HH];
__device__ __align__(16) float g_edge_lin[ETYPES_MAX * HH];
__device__ __align__(16) float g_relmsg[ETYPES_MAX * HH];
__device__ __align__(16) float g_attn2[2 * BMAX * VV];
__device__ float g_beta2[2 * BMAX * MVV];
__device__ __align__(16) float g_pooled[BMAX * HH];
__device__ float g_cnt[BMAX];
__device__ __align__(16) float g_logits2[(size_t)2 * MROWS * VV];        // 42 MB
__device__ __align__(16) __nv_bfloat16 g_A16[(size_t)MROWS * VV];        // 10.5 MB
__device__ __align__(16) __nv_bfloat16 g_B16[(size_t)2 * VV * VV];       // 67 MB

// ---------------- fp32 -> bf16 bulk convert ----------------
__global__ void f2bf_kernel(const float4* __restrict__ src, uint2* __restrict__ dst, int n4)
{
    int i = blockIdx.x * blockDim.x + threadIdx.x;
    if (i >= n4) return;
    float4 v = src[i];
    __nv_bfloat162 lo, hi;
    lo.x = __float2bfloat16(v.x); lo.y = __float2bfloat16(v.y);
    hi.x = __float2bfloat16(v.z); hi.y = __float2bfloat16(v.w);
    uint2 o;
    o.x = *reinterpret_cast<uint32_t*>(&lo);
    o.y = *reinterpret_cast<uint32_t*>(&hi);
    dst[i] = o;
}

// ================= bf16 HMMA GEMM v2: C[r,c] = sum_k A[r,k]*B[c,k] =================
// ldmatrix fragment feeding + cp.async 3-stage pipeline + both layers via grid.z.
// Block tile 128x128, k-step 32. 8 warps (2x4): warp tile 64x32, mma m16n8k16.
// smem operand tile: 128 rows x 32 bf16 (4 x 16B chunks/row), swizzled:
//   off16(r,c) = (r>>1)*128 + ((((r&1)<<2)|c) ^ ((r>>1)&3)) * 16  -> conflict-free ldmatrix.
#define GSTAGE 3
#define OPBYTES 8192
#define STGBYTES (2 * OPBYTES)

__device__ __forceinline__ uint32_t sw_off(int r, int c) {
    return ((uint32_t)(r >> 1) << 7) + ((uint32_t)((((r & 1) << 2) | c) ^ ((r >> 1) & 3)) << 4);
}

__global__ __launch_bounds__(256) void bf16_gemm2_kernel(
    const __nv_bfloat16* __restrict__ A, const __nv_bfloat16* __restrict__ Bbase,
    float* __restrict__ Cbase)
{
    __shared__ __align__(128) char smem[GSTAGE * STGBYTES];
    const __nv_bfloat16* Bm = Bbase + (size_t)blockIdx.z * VV * VV;
    float* C = Cbase + (size_t)blockIdx.z * MROWS * VV;

    const int tid = threadIdx.x;
    const int warpId = tid >> 5, lane = tid & 31;
    const int wr = warpId >> 2, wc = warpId & 3;
    const int gid = lane >> 2, tig = lane & 3;
    const int rbase = blockIdx.y * 128;
    const int cbase = blockIdx.x * 128;

    // copy indices: 2 chunks per operand per thread
    const int r0c = tid >> 2, c0c = tid & 3;           // chunk ids tid and tid+256
    const int r1c = (tid + 256) >> 2, c1c = tid & 3;
    const uint32_t sw0 = sw_off(r0c, c0c), sw1 = sw_off(r1c, c1c);
    const __nv_bfloat16* Ag = A + (size_t)rbase * VV;
    const __nv_bfloat16* Bg = Bm + (size_t)cbase * VV;

    uint32_t sbase;
    asm("{ .reg .u64 t; cvta.to.shared.u64 t, %1; cvt.u32.u64 %0, t; }"
        : "=r"(sbase) : "l"((const void*)smem));

    // ldmatrix lane offsets (relative to operand buffer base), per (mf/p, ks)
    uint32_t offA[4][2], offB[2][2];
    {
        int ar = wr * 64 + (lane & 15);
        int ac = lane >> 4;
#pragma unroll
        for (int mf = 0; mf < 4; mf++)
#pragma unroll
            for (int ks = 0; ks < 2; ks++)
                offA[mf][ks] = sw_off(ar + mf * 16, 2 * ks + ac);
        int br = wc * 32 + ((lane >> 4) << 3) + (lane & 7);
        int bc = (lane >> 3) & 1;
#pragma unroll
        for (int p = 0; p < 2; p++)
#pragma unroll
            for (int ks = 0; ks < 2; ks++)
                offB[p][ks] = sw_off(br + p * 16, 2 * ks + bc);
    }

    float acc[4][4][4];
#pragma unroll
    for (int i = 0; i < 4; i++)
#pragma unroll
        for (int j = 0; j < 4; j++)
#pragma unroll
            for (int q = 0; q < 4; q++) acc[i][j][q] = 0.f;

#define ISSUE_STAGE(s, kbase)                                                          \
    do {                                                                               \
        uint32_t da = sbase + (s) * STGBYTES;                                          \
        uint32_t db = da + OPBYTES;                                                    \
        asm volatile("cp.async.cg.shared.global [%0], [%1], 16;" ::                    \
            "r"(da + sw0), "l"(Ag + (size_t)r0c * VV + (kbase) + c0c * 8));            \
        asm volatile("cp.async.cg.shared.global [%0], [%1], 16;" ::                    \
            "r"(da + sw1), "l"(Ag + (size_t)r1c * VV + (kbase) + c1c * 8));            \
        asm volatile("cp.async.cg.shared.global [%0], [%1], 16;" ::                    \
            "r"(db + sw0), "l"(Bg + (size_t)r0c * VV + (kbase) + c0c * 8));            \
        asm volatile("cp.async.cg.shared.global [%0], [%1], 16;" ::                    \
            "r"(db + sw1), "l"(Bg + (size_t)r1c * VV + (kbase) + c1c * 8));            \
    } while (0)

    ISSUE_STAGE(0, 0);
    asm volatile("cp.async.commit_group;" ::: "memory");
    ISSUE_STAGE(1, 32);
    asm volatile("cp.async.commit_group;" ::: "memory");

    const int NIT = VV / 32;  // 128
    int buf = 0;
    for (int kt = 0; kt < NIT; kt++) {
        asm volatile("cp.async.wait_group 1;" ::: "memory");
        __syncthreads();
        uint32_t sa = sbase + buf * STGBYTES;
        uint32_t sb = sa + OPBYTES;

#pragma unroll
        for (int ks = 0; ks < 2; ks++) {
            uint32_t af[4][4], bq[2][4];
#pragma unroll
            for (int mf = 0; mf < 4; mf++)
                asm volatile("ldmatrix.sync.aligned.m8n8.x4.shared.b16 {%0,%1,%2,%3}, [%4];"
                             : "=r"(af[mf][0]), "=r"(af[mf][1]), "=r"(af[mf][2]), "=r"(af[mf][3])
                             : "r"(sa + offA[mf][ks]));
#pragma unroll
            for (int p = 0; p < 2; p++)
                asm volatile("ldmatrix.sync.aligned.m8n8.x4.shared.b16 {%0,%1,%2,%3}, [%4];"
                             : "=r"(bq[p][0]), "=r"(bq[p][1]), "=r"(bq[p][2]), "=r"(bq[p][3])
                             : "r"(sb + offB[p][ks]));
#pragma unroll
            for (int mf = 0; mf < 4; mf++)
#pragma unroll
                for (int nf = 0; nf < 4; nf++) {
                    const uint32_t b0 = bq[nf >> 1][(nf & 1) * 2];
                    const uint32_t b1 = bq[nf >> 1][(nf & 1) * 2 + 1];
                    asm volatile(
                        "mma.sync.aligned.m16n8k16.row.col.f32.bf16.bf16.f32 "
                        "{%0,%1,%2,%3}, {%4,%5,%6,%7}, {%8,%9}, {%0,%1,%2,%3};"
                        : "+f"(acc[mf][nf][0]), "+f"(acc[mf][nf][1]),
                          "+f"(acc[mf][nf][2]), "+f"(acc[mf][nf][3])
                        : "r"(af[mf][0]), "r"(af[mf][1]), "r"(af[mf][2]), "r"(af[mf][3]),
                          "r"(b0), "r"(b1));
                }
        }

        if (kt + 2 < NIT) {
            int ps = (kt + 2) % GSTAGE;
            ISSUE_STAGE(ps, (kt + 2) * 32);
        }
        asm volatile("cp.async.commit_group;" ::: "memory");
        buf = (buf + 1) % GSTAGE;
    }

#pragma unroll
    for (int mf = 0; mf < 4; mf++) {
        int r0 = rbase + wr * 64 + mf * 16 + gid;
#pragma unroll
        for (int nf = 0; nf < 4; nf++) {
            int c0 = cbase + wc * 32 + nf * 8 + tig * 2;
            *reinterpret_cast<float2*>(C + (size_t)r0 * VV + c0) =
                make_float2(acc[mf][nf][0], acc[mf][nf][1]);
            *reinterpret_cast<float2*>(C + (size_t)(r0 + 8) * VV + c0) =
                make_float2(acc[mf][nf][2], acc[mf][nf][3]);
        }
    }
}

// ---------------- softmax over MV + beta reduce (both layers via grid.z) ----------------
__global__ __launch_bounds__(256) void softmax_beta_kernel(
    const float* __restrict__ logits, const float* __restrict__ beta,
    float* __restrict__ attn, int B)
{
    __shared__ float sBeta[MVV];
    const int l = blockIdx.z;
    const int b = blockIdx.y;
    const int v = blockIdx.x * 256 + threadIdx.x;
    if (threadIdx.x < MVV) sBeta[threadIdx.x] = beta[(l * B + b) * MVV + threadIdx.x];
    __syncthreads();
    const float* lp = logits + (size_t)l * MROWS * VV + (size_t)b * MVV * VV + v;
    float z[MVV];
    float mx = -1e30f;
#pragma unroll
    for (int m = 0; m < MVV; m++) {
        z[m] = lp[(size_t)m * VV];
        mx = fmaxf(mx, z[m]);
    }
    float se = 0.f, sw = 0.f;
#pragma unroll
    for (int m = 0; m < MVV; m++) {
        float e = __expf(z[m] - mx);
        se += e;
        sw += e * sBeta[m];
    }
    attn[(size_t)l * B * VV + (size_t)b * VV + v] = sw / se;
}

// ---------------- beta (both layers): tanh(vn . bw_l + bb_l) * exp(0.01*(MV-mv)) ----------------
__global__ void beta_kernel(const float* __restrict__ vn, const float* __restrict__ bw,
                            const float* __restrict__ bb, float* __restrict__ beta, int BMV)
{
    int gw = (blockIdx.x * blockDim.x + threadIdx.x) >> 5;
    int lane = threadIdx.x & 31;
    if (gw >= 2 * BMV) return;
    int l = gw / BMV, rowid = gw % BMV;
    int mv = rowid % MVV;
    const float* row = vn + (size_t)rowid * VV;
    const float* bwl = bw + (size_t)l * VV;
    float s = 0.f;
    for (int k = lane; k < VV; k += 32) s = fmaf(row[k], bwl[k], s);
#pragma unroll
    for (int o = 16; o > 0; o >>= 1) s += __shfl_xor_sync(0xffffffffu, s, o);
    if (lane == 0) beta[gw] = tanhf(s + bb[l]) * __expf(0.01f * (float)(MVV - mv));
}

// ---------------- generic out[r,c] = act( (a1[r,:] + s*a2[r,:]) @ w[c,:] + bias[c] ), K=N=128 ----------------
__global__ __launch_bounds__(256) void gemm128_kernel(
    const float* __restrict__ a1, const float* __restrict__ a2,
    const float* __restrict__ epsp, int layer,
    const float* __restrict__ w, const float* __restrict__ bias,
    float* __restrict__ out, int M, int relu)
{
    __shared__ float sIn[128][33];
    __shared__ float sW[128][33];
    const int tid = threadIdx.x;
    const int rg = tid >> 4, cg = tid & 15;
    const int rbase = blockIdx.x * 128;
    float scale = 0.f;
    if (a2) scale = 1.0f + epsp[layer];

    float acc[8][8];
#pragma unroll
    for (int i = 0; i < 8; i++)
#pragma unroll
        for (int j = 0; j < 8; j++) acc[i][j] = 0.f;

    for (int k0 = 0; k0 < 128; k0 += 32) {
#pragma unroll
        for (int f = tid; f < 1024; f += 256) {
            int row = f >> 3, c4 = f & 7;
            int r = rbase + row;
            float4 v = make_float4(0.f, 0.f, 0.f, 0.f);
            if (r < M) {
                v = *reinterpret_cast<const float4*>(a1 + (size_t)r * 128 + k0 + c4 * 4);
                if (a2) {
                    float4 u = *reinterpret_cast<const float4*>(a2 + (size_t)r * 128 + k0 + c4 * 4);
                    v.x = fmaf(scale, u.x, v.x); v.y = fmaf(scale, u.y, v.y);
                    v.z = fmaf(scale, u.z, v.z); v.w = fmaf(scale, u.w, v.w);
                }
            }
            float* p = &sIn[row][c4 * 4];
            p[0] = v.x; p[1] = v.y; p[2] = v.z; p[3] = v.w;
        }
#pragma unroll
        for (int f = tid; f < 1024; f += 256) {
            int row = f >> 3, c4 = f & 7;
            float4 v = *reinterpret_cast<const float4*>(w + (size_t)row * 128 + k0 + c4 * 4);
            float* p = &sW[row][c4 * 4];
            p[0] = v.x; p[1] = v.y; p[2] = v.z; p[3] = v.w;
        }
        __syncthreads();
#pragma unroll 4
        for (int k = 0; k < 32; k++) {
            float aa[8], bb[8];
#pragma unroll
            for (int i = 0; i < 8; i++) aa[i] = sIn[rg + 16 * i][k];
#pragma unroll
            for (int i = 0; i < 8; i++) bb[i] = sW[cg + 16 * i][k];
#pragma unroll
            for (int i = 0; i < 8; i++)
#pragma unroll
                for (int j = 0; j < 8; j++) acc[i][j] = fmaf(aa[i], bb[j], acc[i][j]);
        }
        __syncthreads();
    }
#pragma unroll
    for (int i = 0; i < 8; i++) {
        int r = rbase + rg + 16 * i;
        if (r >= M) continue;
#pragma unroll
        for (int j = 0; j < 8; j++) {
            int c = cg + 16 * j;
            float v = acc[i][j] + bias[c];
            if (relu) v = fmaxf(v, 0.f);
            out[(size_t)r * 128 + c] = v;
        }
    }
}

// ---------------- relmsg[t,:] = (edge_lin[t,:] . wrw + wrb) * edge_lin[t,:] ----------------
__global__ void relmsg_kernel(const float* __restrict__ el, const float* __restrict__ wrw,
                              const float* __restrict__ wrb, float* __restrict__ rm)
{
    int t = blockIdx.x, tid = threadIdx.x;  // 128 threads
    __shared__ float warpred[4];
    __shared__ float wsh;
    float v = el[(size_t)t * HH + tid];
    float p = v * wrw[tid];
#pragma unroll
    for (int o = 16; o > 0; o >>= 1) p += __shfl_xor_sync(0xffffffffu, p, o);
    if ((tid & 31) == 0) warpred[tid >> 5] = p;
    __syncthreads();
    if (tid == 0) wsh = warpred[0] + warpred[1] + warpred[2] + warpred[3] + wrb[0];
    __syncthreads();
    rm[(size_t)t * HH + tid] = wsh * v;
}

// ---------------- x0 gather: x[i,:] = node_lin[node_ids[i],:] ----------------
__global__ void gather_kernel(const int* __restrict__ nids, const float* __restrict__ nl,
                              float* __restrict__ x, int n)
{
    int gt = blockIdx.x * blockDim.x + threadIdx.x;
    int i = gt >> 5;
    if (i >= n) return;
    int lane = gt & 31;
    *reinterpret_cast<float4*>(x + (size_t)i * HH + lane * 4) =
        *reinterpret_cast<const float4*>(nl + (size_t)__ldg(nids + i) * HH + lane * 4);
}

// ---------------- edge message + scatter: agg[dst] += relu(a*x[src] + relmsg[type]) ----------------
__global__ void msg_kernel(const int* __restrict__ ei, const int* __restrict__ eids,
                           const int* __restrict__ nids, const int* __restrict__ batch,
                           const float* __restrict__ attn, const float* __restrict__ x,
                           const float* __restrict__ relmsg, float* __restrict__ agg, int E)
{
    int gt = blockIdx.x * blockDim.x + threadIdx.x;
    int e = gt >> 5;
    if (e >= E) return;
    int lane = gt & 31;
    int src = __ldg(ei + e);
    int dst = __ldg(ei + E + e);
    int t = __ldg(eids + e);
    float a = __ldg(attn + (size_t)__ldg(batch + src) * VV + __ldg(nids + src));
    float4 xv = *reinterpret_cast<const float4*>(x + (size_t)src * HH + lane * 4);
    float4 rm = __ldg(reinterpret_cast<const float4*>(relmsg + (size_t)t * HH + lane * 4));
    float m0 = fmaxf(fmaf(a, xv.x, rm.x), 0.f);
    float m1 = fmaxf(fmaf(a, xv.y, rm.y), 0.f);
    float m2 = fmaxf(fmaf(a, xv.z, rm.z), 0.f);
    float m3 = fmaxf(fmaf(a, xv.w, rm.w), 0.f);
    float* p = agg + (size_t)dst * HH + lane * 4;
    asm volatile("red.global.add.v4.f32 [%0], {%1,%2,%3,%4};"
                 :: "l"(p), "f"(m0), "f"(m1), "f"(m2), "f"(m3) : "memory");
}

// ---------------- mean-pool accumulation ----------------
__global__ void pool_kernel(const int* __restrict__ batch, const float* __restrict__ x,
                            float* __restrict__ pooled, float* __restrict__ cnt, int n)
{
    int gt = blockIdx.x * blockDim.x + threadIdx.x;
    int i = gt >> 5;
    if (i >= n) return;
    int lane = gt & 31;
    int b = __ldg(batch + i);
    float4 v = *reinterpret_cast<const float4*>(x + (size_t)i * HH + lane * 4);
    float* p = pooled + (size_t)b * HH + lane * 4;
    asm volatile("red.global.add.v4.f32 [%0], {%1,%2,%3,%4};"
                 :: "l"(p), "f"(v.x), "f"(v.y), "f"(v.z), "f"(v.w) : "memory");
    if (lane == 0) atomicAdd(cnt + b, 1.0f);
}

// ---------------- per-graph head: mean pool, node branch, MLP ----------------
__global__ __launch_bounds__(128) void final_kernel(
    const float* __restrict__ ehr, const float* __restrict__ nemb,
    const float* __restrict__ lw, const float* __restrict__ lb,
    const float* __restrict__ pooled, const float* __restrict__ cnt,
    const float* __restrict__ mw, const float* __restrict__ mb,
    float* __restrict__ out)
{
    int b = blockIdx.x, tid = threadIdx.x;
    __shared__ float sE[128];
    __shared__ float cat[256];
    __shared__ float red4[4];
    __shared__ float sSum;
    const float* eb = ehr + (size_t)b * VV;

    float s = 0.f;
    for (int v = tid; v < VV; v += 128) s += eb[v];
#pragma unroll
    for (int o = 16; o > 0; o >>= 1) s += __shfl_xor_sync(0xffffffffu, s, o);
    if ((tid & 31) == 0) red4[tid >> 5] = s;
    __syncthreads();
    if (tid == 0) sSum = red4[0] + red4[1] + red4[2] + red4[3];
    __syncthreads();

    float accd = 0.f;
    for (int v0 = 0; v0 < VV; v0 += 128) {
        __syncthreads();
        sE[tid] = eb[v0 + tid];
        __syncthreads();
#pragma unroll 8
        for (int vv = 0; vv < 128; vv++)
            accd = fmaf(sE[vv], nemb[(size_t)(v0 + vv) * HH + tid], accd);
    }
    accd /= sSum;
    __syncthreads();
    sE[tid] = accd;
    __syncthreads();

    float xl = lb[tid];
#pragma unroll 8
    for (int d = 0; d < 128; d++) xl = fmaf(sE[d], lw[(size_t)tid * 128 + d], xl);
    cat[128 + tid] = xl;
    float c = fmaxf(cnt[b], 1.0f);
    cat[tid] = pooled[(size_t)b * HH + tid] / c;
    __syncthreads();
    if (tid < 25) {
        float o = mb[tid];
#pragma unroll 8
        for (int j = 0; j < 256; j++) o = fmaf(cat[j], mw[(size_t)tid * 256 + j], o);
        out[b * 25 + tid] = o;
    }
}

// ---------------- launch ----------------
extern "C" void kernel_launch(void* const* d_in, const int* in_sizes, int n_in,
                              void* d_out, int out_size)
{
    const int*   node_ids   = (const int*)d_in[0];
    const int*   edge_ids   = (const int*)d_in[1];
    const int*   edge_index = (const int*)d_in[2];
    const float* visit_node = (const float*)d_in[6];
    const float* ehr        = (const float*)d_in[7];
    const int*   batch      = (const int*)d_in[8];
    const float* node_emb   = (const float*)d_in[10];
    const float* edge_emb   = (const float*)d_in[11];
    const float* lin_w      = (const float*)d_in[12];
    const float* lin_b      = (const float*)d_in[13];
    const float* alpha_w    = (const float*)d_in[14];
    const float* beta_w     = (const float*)d_in[16];
    const float* beta_b     = (const float*)d_in[17];
    const float* conv_w     = (const float*)d_in[18];
    const float* conv_b     = (const float*)d_in[19];
    const float* wr_w       = (const float*)d_in[20];
    const float* wr_b       = (const float*)d_in[21];
    const float* epsp       = (const float*)d_in[22];
    const float* mlp_w      = (const float*)d_in[23];
    const float* mlp_b      = (const float*)d_in[24];

    const int N = in_sizes[0];
    const int E = in_sizes[1];
    const int B = in_sizes[7] / VV;
    const int NT = in_sizes[11] / HH;  // edge-type count (500)
    const int AW = in_sizes[14];       // 2*4096*4096
    const int VN = in_sizes[6];        // B*MV*4096

    float *xA, *xB, *nl, *elin, *rm, *attn2, *beta2, *pooled, *cnt, *logits2;
    __nv_bfloat16 *A16, *B16;
    cudaGetSymbolAddress((void**)&xA, g_xA);
    cudaGetSymbolAddress((void**)&xB, g_xB);
    cudaGetSymbolAddress((void**)&nl, g_node_lin);
    cudaGetSymbolAddress((void**)&elin, g_edge_lin);
    cudaGetSymbolAddress((void**)&rm, g_relmsg);
    cudaGetSymbolAddress((void**)&attn2, g_attn2);
    cudaGetSymbolAddress((void**)&beta2, g_beta2);
    cudaGetSymbolAddress((void**)&pooled, g_pooled);
    cudaGetSymbolAddress((void**)&cnt, g_cnt);
    cudaGetSymbolAddress((void**)&logits2, g_logits2);
    cudaGetSymbolAddress((void**)&A16, g_A16);
    cudaGetSymbolAddress((void**)&B16, g_B16);

    // one-time bf16 conversions (bandwidth-bound)
    f2bf_kernel<<<(VN / 4 + 255) / 256, 256>>>(
        (const float4*)visit_node, (uint2*)A16, VN / 4);
    f2bf_kernel<<<(AW / 4 + 255) / 256, 256>>>(
        (const float4*)alpha_w, (uint2*)B16, AW / 4);

    // both layers' attention path hoisted out of the serial loop
    beta_kernel<<<(2 * B * MVV * 32 + 255) / 256, 256>>>(visit_node, beta_w, beta_b,
                                                         beta2, B * MVV);
    bf16_gemm2_kernel<<<dim3(VV / 128, MROWS / 128, 2), 256>>>(A16, B16, logits2);
    softmax_beta_kernel<<<dim3(VV / 256, B, 2), 256>>>(logits2, beta2, attn2, B);

    // vocabulary-level precompute (4096 + 500 rows instead of 50000 + 800000)
    gemm128_kernel<<<(VV + 127) / 128, 256>>>(node_emb, nullptr, nullptr, 0, lin_w, lin_b, nl, VV, 0);
    gemm128_kernel<<<(NT + 127) / 128, 256>>>(edge_emb, nullptr, nullptr, 0, lin_w, lin_b, elin, NT, 0);
    gather_kernel<<<(N * 32 + 255) / 256, 256>>>(node_ids, nl, xA, N);

    for (int l = 0; l < 2; l++) {
        float* xcur = (l == 0) ? xA : xB;
        float* aggb = (l == 0) ? xB : xA;
        relmsg_kernel<<<NT, 128>>>(elin, wr_w + (size_t)l * HH, wr_b + l, rm);
        cudaMemsetAsync(aggb, 0, (size_t)N * HH * sizeof(float));
        msg_kernel<<<(E * 32 + 255) / 256, 256>>>(edge_index, edge_ids, node_ids, batch,
                                                  attn2 + (size_t)l * B * VV, xcur, rm, aggb, E);
        // in-place: each block only reads/writes its own 128 rows, writes after all reads
        gemm128_kernel<<<(N + 127) / 128, 256>>>(aggb, xcur, epsp, l,
                                                 conv_w + (size_t)l * HH * HH, conv_b + (size_t)l * HH,
                                                 aggb, N, 1);
    }

    cudaMemsetAsync(pooled, 0, (size_t)BMAX * HH * sizeof(float));
    cudaMemsetAsync(cnt, 0, BMAX * sizeof(float));
    pool_kernel<<<(N * 32 + 255) / 256, 256>>>(batch, xA, pooled, cnt, N);
    final_kernel<<<B, 128>>>(ehr, node_emb, lin_w, lin_b, pooled, cnt, mlp_w, mlp_b, (float*)d_out);
}